// round 6
// baseline (speedup 1.0000x reference)
#include <cuda_runtime.h>
#include <cuda_bf16.h>

// 2-layer GCN via CSC build + gather aggregation (no FP atomics anywhere).
// edge_index arrives as int32 (JAX x64 disabled).
// 6 kernels: gemm1 | edge_count | scan_fused(dinv+offsets) | fill | layer1 | layer2

#define N_NODES 100000
#define N_EDGES 1600000
#define C 64
#define SCAN_B 256
#define NB ((N_NODES + SCAN_B - 1) / SCAN_B)   // 391
#define W_SCALE 67108864.0f                    // 2^26 fixed-point for w
#define W_MASK  ((1ULL << 40) - 1ULL)
#define GB 64                                   // gemm nodes per block
#define GEMM_GRID ((N_NODES + GB - 1) / GB)    // 1563

__device__ unsigned long long g_pack[N_NODES];   // {cnt:24 | sum_w fixed:40}
__device__ float g_dinv[N_NODES];
__device__ int   g_off[N_NODES + 1];
__device__ int   g_cursor[N_NODES];
__device__ unsigned long long g_scanstate[NB];   // {flag:2 | value:32}
__device__ __align__(16) uint2 g_edge[N_EDGES];           // {src, coef bits}
__device__ __align__(16) float g_h[(size_t)N_NODES * C];
__device__ float g_s[N_NODES];

// h = x @ W1, register-tiled: 64 nodes x 64 ch per block, 4x4 per thread.
// Also zeroes g_pack (grid*256 = 400k threads >= N_NODES).
__global__ void k_gemm1(const float* __restrict__ x,
                        const float* __restrict__ W1) {
    __shared__ float xs[GB][72];
    __shared__ float Ws[64][64];
    int t = threadIdx.x;
    int nb = blockIdx.x * GB;

    int gi = blockIdx.x * 256 + t;
    if (gi < N_NODES) g_pack[gi] = 0ULL;

#pragma unroll
    for (int i = 0; i < 16; i++)
        ((float*)Ws)[t + i * 256] = W1[t + i * 256];

    {
        int nd = t >> 2;
        int q  = (t & 3) * 16;
        int node = nb + nd;
        if (node < N_NODES) {
            const float* xp = x + (size_t)node * 64 + q;
            float4 v0 = *(const float4*)(xp);
            float4 v1 = *(const float4*)(xp + 4);
            float4 v2 = *(const float4*)(xp + 8);
            float4 v3 = *(const float4*)(xp + 12);
            *(float4*)&xs[nd][q]      = v0;
            *(float4*)&xs[nd][q + 4]  = v1;
            *(float4*)&xs[nd][q + 8]  = v2;
            *(float4*)&xs[nd][q + 12] = v3;
        }
    }
    __syncthreads();

    int ch4 = (t & 15) * 4;
    int nd0 = (t >> 4) * 4;

    float acc[4][4];
#pragma unroll
    for (int i = 0; i < 4; i++)
#pragma unroll
        for (int j = 0; j < 4; j++) acc[i][j] = 0.0f;

#pragma unroll 4
    for (int k = 0; k < 64; k++) {
        float4 wv = *(const float4*)&Ws[k][ch4];
        float x0 = xs[nd0 + 0][k];
        float x1 = xs[nd0 + 1][k];
        float x2 = xs[nd0 + 2][k];
        float x3 = xs[nd0 + 3][k];
        acc[0][0] = fmaf(x0, wv.x, acc[0][0]); acc[0][1] = fmaf(x0, wv.y, acc[0][1]);
        acc[0][2] = fmaf(x0, wv.z, acc[0][2]); acc[0][3] = fmaf(x0, wv.w, acc[0][3]);
        acc[1][0] = fmaf(x1, wv.x, acc[1][0]); acc[1][1] = fmaf(x1, wv.y, acc[1][1]);
        acc[1][2] = fmaf(x1, wv.z, acc[1][2]); acc[1][3] = fmaf(x1, wv.w, acc[1][3]);
        acc[2][0] = fmaf(x2, wv.x, acc[2][0]); acc[2][1] = fmaf(x2, wv.y, acc[2][1]);
        acc[2][2] = fmaf(x2, wv.z, acc[2][2]); acc[2][3] = fmaf(x2, wv.w, acc[2][3]);
        acc[3][0] = fmaf(x3, wv.x, acc[3][0]); acc[3][1] = fmaf(x3, wv.y, acc[3][1]);
        acc[3][2] = fmaf(x3, wv.z, acc[3][2]); acc[3][3] = fmaf(x3, wv.w, acc[3][3]);
    }

#pragma unroll
    for (int i = 0; i < 4; i++) {
        int node = nb + nd0 + i;
        if (node < N_NODES) {
            float4 o = make_float4(acc[i][0], acc[i][1], acc[i][2], acc[i][3]);
            *(float4*)(g_h + (size_t)node * 64 + ch4) = o;
        }
    }
}

// one packed u64 atomic per edge; also zeroes scan state for the next kernel
__global__ void k_edge_count(const int* __restrict__ ei,
                             const float* __restrict__ w) {
    int t = blockIdx.x * blockDim.x + threadIdx.x;
    if (t < NB) g_scanstate[t] = 0ULL;
    if (t * 2 >= N_EDGES) return;
    int2   cc = *reinterpret_cast<const int2*>(ei + N_EDGES + t * 2);
    float2 ww = *reinterpret_cast<const float2*>(w + t * 2);
    unsigned long long p0 = (1ULL << 40) + (unsigned long long)(ww.x * W_SCALE);
    unsigned long long p1 = (1ULL << 40) + (unsigned long long)(ww.y * W_SCALE);
    atomicAdd(&g_pack[cc.x], p0);
    atomicAdd(&g_pack[cc.y], p1);
}

// fused: dinv + exclusive scan of counts (decoupled lookback) + cursor init
__global__ void k_scan_fused() {
    int t = threadIdx.x;
    int b = blockIdx.x;
    int i = b * SCAN_B + t;
    int lane = t & 31, wid = t >> 5;

    int cnt = 0;
    if (i < N_NODES) {
        unsigned long long p = g_pack[i];
        cnt = (int)(p >> 40);
        float deg = 1.0f + (float)(p & W_MASK) * (1.0f / W_SCALE);
        g_dinv[i] = rsqrtf(deg);
    }

    // block-wide inclusive scan (warp shuffles)
    int v = cnt;
#pragma unroll
    for (int o = 1; o < 32; o <<= 1) {
        int y = __shfl_up_sync(0xffffffffu, v, o);
        if (lane >= o) v += y;
    }
    __shared__ int wsum[8];
    if (lane == 31) wsum[wid] = v;
    __syncthreads();
    if (wid == 0) {
        int x = (lane < 8) ? wsum[lane] : 0;
#pragma unroll
        for (int o = 1; o < 8; o <<= 1) {
            int y = __shfl_up_sync(0xffffffffu, x, o);
            if (lane >= o) x += y;
        }
        if (lane < 8) wsum[lane] = x;
    }
    __syncthreads();
    int incl = v + ((wid > 0) ? wsum[wid - 1] : 0);
    int blocktotal = wsum[7];

    __shared__ int sh_prefix;
    if (t == 0) {
        if (b == 0) {
            sh_prefix = 0;
            atomicExch(&g_scanstate[0], (2ULL << 62) | (unsigned)blocktotal);
        } else {
            atomicExch(&g_scanstate[b], (1ULL << 62) | (unsigned)blocktotal);
            int ex = 0;
            int j = b - 1;
            for (;;) {
                unsigned long long s;
                do { s = atomicAdd(&g_scanstate[j], 0ULL); } while ((s >> 62) == 0ULL);
                ex += (int)(s & 0xffffffffULL);
                if ((s >> 62) == 2ULL) break;
                j--;
            }
            sh_prefix = ex;
            atomicExch(&g_scanstate[b], (2ULL << 62) | (unsigned)(ex + blocktotal));
        }
    }
    __syncthreads();

    if (i < N_NODES) {
        int off = sh_prefix + incl - cnt;   // exclusive
        g_off[i] = off;
        g_cursor[i] = off;
    }
    if (i == 0) g_off[N_NODES] = N_EDGES;
}

__global__ void k_fill(const int* __restrict__ ei,
                       const float* __restrict__ w) {
    int t = blockIdx.x * blockDim.x + threadIdx.x;
    if (t * 2 >= N_EDGES) return;
    int2   rr = *reinterpret_cast<const int2*>(ei + t * 2);
    int2   cc = *reinterpret_cast<const int2*>(ei + N_EDGES + t * 2);
    float2 ww = *reinterpret_cast<const float2*>(w + t * 2);
    float coef0 = g_dinv[rr.x] * ww.x;
    float coef1 = g_dinv[rr.y] * ww.y;
    int p0 = atomicAdd(&g_cursor[cc.x], 1);
    g_edge[p0] = make_uint2((unsigned)rr.x, __float_as_uint(coef0));
    int p1 = atomicAdd(&g_cursor[cc.y], 1);
    g_edge[p1] = make_uint2((unsigned)rr.y, __float_as_uint(coef1));
}

// fused layer1 aggregate + relu + layer2 projection. one warp per node.
// 8-deep edge unroll for MLP (16 independent loads in flight).
__global__ void k_layer1(const float* __restrict__ b1,
                         const float* __restrict__ W2) {
    int n = (blockIdx.x * blockDim.x + threadIdx.x) >> 5;
    int lane = threadIdx.x & 31;
    if (n >= N_NODES) return;

    int idx = g_off[n];
    int end = g_off[n + 1];
    const float2* __restrict__ hp = reinterpret_cast<const float2*>(g_h);

    float a0 = 0.0f, a1 = 0.0f;
    for (; idx + 8 <= end; idx += 8) {
        uint2 e0 = g_edge[idx + 0];
        uint2 e1 = g_edge[idx + 1];
        uint2 e2 = g_edge[idx + 2];
        uint2 e3 = g_edge[idx + 3];
        uint2 e4 = g_edge[idx + 4];
        uint2 e5 = g_edge[idx + 5];
        uint2 e6 = g_edge[idx + 6];
        uint2 e7 = g_edge[idx + 7];
        float2 h0 = hp[e0.x * 32u + lane];
        float2 h1 = hp[e1.x * 32u + lane];
        float2 h2 = hp[e2.x * 32u + lane];
        float2 h3 = hp[e3.x * 32u + lane];
        float2 h4 = hp[e4.x * 32u + lane];
        float2 h5 = hp[e5.x * 32u + lane];
        float2 h6 = hp[e6.x * 32u + lane];
        float2 h7 = hp[e7.x * 32u + lane];
        float c0 = __uint_as_float(e0.y), c1 = __uint_as_float(e1.y);
        float c2 = __uint_as_float(e2.y), c3 = __uint_as_float(e3.y);
        float c4 = __uint_as_float(e4.y), c5 = __uint_as_float(e5.y);
        float c6 = __uint_as_float(e6.y), c7 = __uint_as_float(e7.y);
        a0 = fmaf(c0, h0.x, a0); a1 = fmaf(c0, h0.y, a1);
        a0 = fmaf(c1, h1.x, a0); a1 = fmaf(c1, h1.y, a1);
        a0 = fmaf(c2, h2.x, a0); a1 = fmaf(c2, h2.y, a1);
        a0 = fmaf(c3, h3.x, a0); a1 = fmaf(c3, h3.y, a1);
        a0 = fmaf(c4, h4.x, a0); a1 = fmaf(c4, h4.y, a1);
        a0 = fmaf(c5, h5.x, a0); a1 = fmaf(c5, h5.y, a1);
        a0 = fmaf(c6, h6.x, a0); a1 = fmaf(c6, h6.y, a1);
        a0 = fmaf(c7, h7.x, a0); a1 = fmaf(c7, h7.y, a1);
    }
    for (; idx < end; idx++) {
        uint2 e = g_edge[idx];
        float2 hv = hp[e.x * 32u + lane];
        float cf = __uint_as_float(e.y);
        a0 = fmaf(cf, hv.x, a0);
        a1 = fmaf(cf, hv.y, a1);
    }

    float din = g_dinv[n];
    float2 hn = hp[(unsigned)n * 32u + lane];
    float v0 = fmaxf(fmaf(a0, din, hn.x * din * din) + b1[lane * 2],     0.0f);
    float v1 = fmaxf(fmaf(a1, din, hn.y * din * din) + b1[lane * 2 + 1], 0.0f);
    float s = v0 * W2[lane * 2] + v1 * W2[lane * 2 + 1];
#pragma unroll
    for (int off = 16; off > 0; off >>= 1)
        s += __shfl_xor_sync(0xffffffffu, s, off);
    if (lane == 0) g_s[n] = s;
}

// layer2 gather: one warp per node, lanes parallel over edges.
__global__ void k_layer2(const float* __restrict__ b2,
                         float* __restrict__ out) {
    int n = (blockIdx.x * blockDim.x + threadIdx.x) >> 5;
    int lane = threadIdx.x & 31;
    if (n >= N_NODES) return;

    int begin = g_off[n];
    int end   = g_off[n + 1];

    float acc = 0.0f;
    for (int idx = begin + lane; idx < end; idx += 32) {
        uint2 em = g_edge[idx];
        acc = fmaf(__uint_as_float(em.y), g_s[em.x], acc);
    }
#pragma unroll
    for (int off = 16; off > 0; off >>= 1)
        acc += __shfl_xor_sync(0xffffffffu, acc, off);

    if (lane == 0) {
        float din = g_dinv[n];
        out[n] = fmaf(acc, din, g_s[n] * din * din) + b2[0];
    }
}

extern "C" void kernel_launch(void* const* d_in, const int* in_sizes, int n_in,
                              void* d_out, int out_size) {
    const float* x  = (const float*)d_in[0];
    const int*   ei = (const int*)d_in[1];
    const float* w  = (const float*)d_in[2];
    const float* W1 = (const float*)d_in[3];
    const float* b1 = (const float*)d_in[4];
    const float* W2 = (const float*)d_in[5];
    const float* b2 = (const float*)d_in[6];
    float* out = (float*)d_out;

    const int T = 256;
    k_gemm1<<<GEMM_GRID, T>>>(x, W1);                       // also zeros g_pack
    k_edge_count<<<(N_EDGES / 2 + T - 1) / T, T>>>(ei, w);  // also zeros scan state
    k_scan_fused<<<NB, SCAN_B>>>();
    k_fill<<<(N_EDGES / 2 + T - 1) / T, T>>>(ei, w);
    k_layer1<<<(N_NODES * 32 + T - 1) / T, T>>>(b1, W2);
    k_layer2<<<(N_NODES * 32 + T - 1) / T, T>>>(b2, out);
}

// round 7
// speedup vs baseline: 1.0323x; 1.0323x over previous
#include <cuda_runtime.h>
#include <cuda_bf16.h>

// 2-layer GCN via CSC build + gather aggregation.
// edge_index arrives as int32 (JAX x64 disabled).
// Ranks assigned by the counting atomic (prev value) -> fill needs NO atomics.
// h is pre-scaled by dinv[row] so edge coef is just w[e] (no dinv gather in fill).
// gemm and fill are independent after the scan -> fused into one grid-split kernel.
//
// k_init -> k_edge_count -> k_scan -> k_gemmfill -> k_layer1 -> k_layer2

#define N_NODES 100000
#define N_EDGES 1600000
#define C 64
#define SCAN_B 256
#define NB ((N_NODES + SCAN_B - 1) / SCAN_B)   // 391
#define W_SCALE 67108864.0f                    // 2^26 fixed-point for w
#define W_MASK  ((1ULL << 40) - 1ULL)
#define GB 64
#define GEMM_GRID ((N_NODES + GB - 1) / GB)    // 1563
#define FILL_GRID ((N_EDGES / 2 + 255) / 256)  // 3125

__device__ unsigned long long g_pack[N_NODES];   // {cnt:24 | sum_w fixed:40}
__device__ float g_dinv[N_NODES];
__device__ int   g_off[N_NODES + 1];
__device__ unsigned long long g_scanstate[NB];   // {flag:2 | value:32}
__device__ __align__(16) unsigned g_rank[N_EDGES];
__device__ __align__(16) uint2 g_edge[N_EDGES];           // {src, w bits}
__device__ __align__(16) float g_h[(size_t)N_NODES * C];  // h' = (x@W1)*dinv[row]
__device__ float g_s[N_NODES];                            // s' = s*dinv

__global__ void k_init() {
    int i = blockIdx.x * blockDim.x + threadIdx.x;
    if (i < N_NODES) g_pack[i] = 0ULL;
    if (i < NB) g_scanstate[i] = 0ULL;
}

// one packed u64 atomic per edge; prev count == rank within destination bucket
__global__ void k_edge_count(const int* __restrict__ ei,
                             const float* __restrict__ w) {
    int t = blockIdx.x * blockDim.x + threadIdx.x;
    if (t * 2 >= N_EDGES) return;
    int2   cc = *reinterpret_cast<const int2*>(ei + N_EDGES + t * 2);
    float2 ww = *reinterpret_cast<const float2*>(w + t * 2);
    unsigned long long p0 = (1ULL << 40) + (unsigned long long)(ww.x * W_SCALE);
    unsigned long long p1 = (1ULL << 40) + (unsigned long long)(ww.y * W_SCALE);
    unsigned long long prev0 = atomicAdd(&g_pack[cc.x], p0);
    unsigned long long prev1 = atomicAdd(&g_pack[cc.y], p1);
    uint2 rk = make_uint2((unsigned)(prev0 >> 40), (unsigned)(prev1 >> 40));
    *reinterpret_cast<uint2*>(g_rank + t * 2) = rk;
}

// fused: dinv + exclusive scan of counts (decoupled lookback)
__global__ void k_scan() {
    int t = threadIdx.x;
    int b = blockIdx.x;
    int i = b * SCAN_B + t;
    int lane = t & 31, wid = t >> 5;

    int cnt = 0;
    if (i < N_NODES) {
        unsigned long long p = g_pack[i];
        cnt = (int)(p >> 40);
        float deg = 1.0f + (float)(p & W_MASK) * (1.0f / W_SCALE);
        g_dinv[i] = rsqrtf(deg);
    }

    int v = cnt;
#pragma unroll
    for (int o = 1; o < 32; o <<= 1) {
        int y = __shfl_up_sync(0xffffffffu, v, o);
        if (lane >= o) v += y;
    }
    __shared__ int wsum[8];
    if (lane == 31) wsum[wid] = v;
    __syncthreads();
    if (wid == 0) {
        int x = (lane < 8) ? wsum[lane] : 0;
#pragma unroll
        for (int o = 1; o < 8; o <<= 1) {
            int y = __shfl_up_sync(0xffffffffu, x, o);
            if (lane >= o) x += y;
        }
        if (lane < 8) wsum[lane] = x;
    }
    __syncthreads();
    int incl = v + ((wid > 0) ? wsum[wid - 1] : 0);
    int blocktotal = wsum[7];

    __shared__ int sh_prefix;
    if (t == 0) {
        if (b == 0) {
            sh_prefix = 0;
            atomicExch(&g_scanstate[0], (2ULL << 62) | (unsigned)blocktotal);
        } else {
            atomicExch(&g_scanstate[b], (1ULL << 62) | (unsigned)blocktotal);
            int ex = 0;
            int j = b - 1;
            for (;;) {
                unsigned long long s;
                do { s = atomicAdd(&g_scanstate[j], 0ULL); } while ((s >> 62) == 0ULL);
                ex += (int)(s & 0xffffffffULL);
                if ((s >> 62) == 2ULL) break;
                j--;
            }
            sh_prefix = ex;
            atomicExch(&g_scanstate[b], (2ULL << 62) | (unsigned)(ex + blocktotal));
        }
    }
    __syncthreads();

    if (i < N_NODES) g_off[i] = sh_prefix + incl - cnt;   // exclusive
    if (i == 0) g_off[N_NODES] = N_EDGES;
}

// grid-split kernel: blocks [0, GEMM_GRID) compute h' = (x@W1)*dinv,
// blocks [GEMM_GRID, GEMM_GRID+FILL_GRID) fill the CSC edge array (no atomics).
__global__ void k_gemmfill(const float* __restrict__ x,
                           const float* __restrict__ W1,
                           const int* __restrict__ ei,
                           const float* __restrict__ w) {
    __shared__ float xs[GB][72];
    __shared__ float Ws[64][64];
    int t = threadIdx.x;

    if (blockIdx.x >= GEMM_GRID) {
        // ---- fill part ----
        int t2 = (blockIdx.x - GEMM_GRID) * 256 + t;
        if (t2 * 2 >= N_EDGES) return;
        int2   rr = *reinterpret_cast<const int2*>(ei + t2 * 2);
        int2   cc = *reinterpret_cast<const int2*>(ei + N_EDGES + t2 * 2);
        float2 ww = *reinterpret_cast<const float2*>(w + t2 * 2);
        uint2  rk = *reinterpret_cast<const uint2*>(g_rank + t2 * 2);
        int p0 = g_off[cc.x] + (int)rk.x;
        int p1 = g_off[cc.y] + (int)rk.y;
        g_edge[p0] = make_uint2((unsigned)rr.x, __float_as_uint(ww.x));
        g_edge[p1] = make_uint2((unsigned)rr.y, __float_as_uint(ww.y));
        return;
    }

    // ---- gemm part ----
    int nb = blockIdx.x * GB;
#pragma unroll
    for (int i = 0; i < 16; i++)
        ((float*)Ws)[t + i * 256] = W1[t + i * 256];
    {
        int nd = t >> 2;
        int q  = (t & 3) * 16;
        int node = nb + nd;
        if (node < N_NODES) {
            const float* xp = x + (size_t)node * 64 + q;
            float4 v0 = *(const float4*)(xp);
            float4 v1 = *(const float4*)(xp + 4);
            float4 v2 = *(const float4*)(xp + 8);
            float4 v3 = *(const float4*)(xp + 12);
            *(float4*)&xs[nd][q]      = v0;
            *(float4*)&xs[nd][q + 4]  = v1;
            *(float4*)&xs[nd][q + 8]  = v2;
            *(float4*)&xs[nd][q + 12] = v3;
        }
    }
    __syncthreads();

    int ch4 = (t & 15) * 4;
    int nd0 = (t >> 4) * 4;

    float acc[4][4];
#pragma unroll
    for (int i = 0; i < 4; i++)
#pragma unroll
        for (int j = 0; j < 4; j++) acc[i][j] = 0.0f;

#pragma unroll 4
    for (int k = 0; k < 64; k++) {
        float4 wv = *(const float4*)&Ws[k][ch4];
        float x0 = xs[nd0 + 0][k];
        float x1 = xs[nd0 + 1][k];
        float x2 = xs[nd0 + 2][k];
        float x3 = xs[nd0 + 3][k];
        acc[0][0] = fmaf(x0, wv.x, acc[0][0]); acc[0][1] = fmaf(x0, wv.y, acc[0][1]);
        acc[0][2] = fmaf(x0, wv.z, acc[0][2]); acc[0][3] = fmaf(x0, wv.w, acc[0][3]);
        acc[1][0] = fmaf(x1, wv.x, acc[1][0]); acc[1][1] = fmaf(x1, wv.y, acc[1][1]);
        acc[1][2] = fmaf(x1, wv.z, acc[1][2]); acc[1][3] = fmaf(x1, wv.w, acc[1][3]);
        acc[2][0] = fmaf(x2, wv.x, acc[2][0]); acc[2][1] = fmaf(x2, wv.y, acc[2][1]);
        acc[2][2] = fmaf(x2, wv.z, acc[2][2]); acc[2][3] = fmaf(x2, wv.w, acc[2][3]);
        acc[3][0] = fmaf(x3, wv.x, acc[3][0]); acc[3][1] = fmaf(x3, wv.y, acc[3][1]);
        acc[3][2] = fmaf(x3, wv.z, acc[3][2]); acc[3][3] = fmaf(x3, wv.w, acc[3][3]);
    }

#pragma unroll
    for (int i = 0; i < 4; i++) {
        int node = nb + nd0 + i;
        if (node < N_NODES) {
            float di = g_dinv[node];
            float4 o = make_float4(acc[i][0] * di, acc[i][1] * di,
                                   acc[i][2] * di, acc[i][3] * di);
            *(float4*)(g_h + (size_t)node * 64 + ch4) = o;
        }
    }
}

// fused layer1 aggregate + relu + layer2 projection. one warp per node.
// h is pre-scaled: a = sum w_e * h'[r]. self: h[n]*din^2 = h'[n]*din.
__global__ void k_layer1(const float* __restrict__ b1,
                         const float* __restrict__ W2) {
    int n = (blockIdx.x * blockDim.x + threadIdx.x) >> 5;
    int lane = threadIdx.x & 31;
    if (n >= N_NODES) return;

    int idx = g_off[n];
    int end = g_off[n + 1];
    const float2* __restrict__ hp = reinterpret_cast<const float2*>(g_h);

    float a0 = 0.0f, a1 = 0.0f;
    for (; idx + 8 <= end; idx += 8) {
        uint2 e0 = g_edge[idx + 0];
        uint2 e1 = g_edge[idx + 1];
        uint2 e2 = g_edge[idx + 2];
        uint2 e3 = g_edge[idx + 3];
        uint2 e4 = g_edge[idx + 4];
        uint2 e5 = g_edge[idx + 5];
        uint2 e6 = g_edge[idx + 6];
        uint2 e7 = g_edge[idx + 7];
        float2 h0 = hp[e0.x * 32u + lane];
        float2 h1 = hp[e1.x * 32u + lane];
        float2 h2 = hp[e2.x * 32u + lane];
        float2 h3 = hp[e3.x * 32u + lane];
        float2 h4 = hp[e4.x * 32u + lane];
        float2 h5 = hp[e5.x * 32u + lane];
        float2 h6 = hp[e6.x * 32u + lane];
        float2 h7 = hp[e7.x * 32u + lane];
        float c0 = __uint_as_float(e0.y), c1 = __uint_as_float(e1.y);
        float c2 = __uint_as_float(e2.y), c3 = __uint_as_float(e3.y);
        float c4 = __uint_as_float(e4.y), c5 = __uint_as_float(e5.y);
        float c6 = __uint_as_float(e6.y), c7 = __uint_as_float(e7.y);
        a0 = fmaf(c0, h0.x, a0); a1 = fmaf(c0, h0.y, a1);
        a0 = fmaf(c1, h1.x, a0); a1 = fmaf(c1, h1.y, a1);
        a0 = fmaf(c2, h2.x, a0); a1 = fmaf(c2, h2.y, a1);
        a0 = fmaf(c3, h3.x, a0); a1 = fmaf(c3, h3.y, a1);
        a0 = fmaf(c4, h4.x, a0); a1 = fmaf(c4, h4.y, a1);
        a0 = fmaf(c5, h5.x, a0); a1 = fmaf(c5, h5.y, a1);
        a0 = fmaf(c6, h6.x, a0); a1 = fmaf(c6, h6.y, a1);
        a0 = fmaf(c7, h7.x, a0); a1 = fmaf(c7, h7.y, a1);
    }
    for (; idx < end; idx++) {
        uint2 e = g_edge[idx];
        float2 hv = hp[e.x * 32u + lane];
        float cf = __uint_as_float(e.y);
        a0 = fmaf(cf, hv.x, a0);
        a1 = fmaf(cf, hv.y, a1);
    }

    float din = g_dinv[n];
    float2 hn = hp[(unsigned)n * 32u + lane];
    float v0 = fmaxf(fmaf(a0 + hn.x, din, b1[lane * 2]),     0.0f);
    float v1 = fmaxf(fmaf(a1 + hn.y, din, b1[lane * 2 + 1]), 0.0f);
    float s = v0 * W2[lane * 2] + v1 * W2[lane * 2 + 1];
#pragma unroll
    for (int off = 16; off > 0; off >>= 1)
        s += __shfl_xor_sync(0xffffffffu, s, off);
    if (lane == 0) g_s[n] = s * din;   // store s' = s*dinv
}

// layer2 gather: s is pre-scaled. out = din*sum(w*s'[r]) + s'[n]*din + b2
__global__ void k_layer2(const float* __restrict__ b2,
                         float* __restrict__ out) {
    int n = (blockIdx.x * blockDim.x + threadIdx.x) >> 5;
    int lane = threadIdx.x & 31;
    if (n >= N_NODES) return;

    int begin = g_off[n];
    int end   = g_off[n + 1];

    float acc = 0.0f;
    for (int idx = begin + lane; idx < end; idx += 32) {
        uint2 em = g_edge[idx];
        acc = fmaf(__uint_as_float(em.y), g_s[em.x], acc);
    }
#pragma unroll
    for (int off = 16; off > 0; off >>= 1)
        acc += __shfl_xor_sync(0xffffffffu, acc, off);

    if (lane == 0) {
        float din = g_dinv[n];
        out[n] = fmaf(acc + g_s[n], din, b2[0]);
    }
}

extern "C" void kernel_launch(void* const* d_in, const int* in_sizes, int n_in,
                              void* d_out, int out_size) {
    const float* x  = (const float*)d_in[0];
    const int*   ei = (const int*)d_in[1];
    const float* w  = (const float*)d_in[2];
    const float* W1 = (const float*)d_in[3];
    const float* b1 = (const float*)d_in[4];
    const float* W2 = (const float*)d_in[5];
    const float* b2 = (const float*)d_in[6];
    float* out = (float*)d_out;

    const int T = 256;
    k_init<<<NB, T>>>();
    k_edge_count<<<(N_EDGES / 2 + T - 1) / T, T>>>(ei, w);
    k_scan<<<NB, SCAN_B>>>();
    k_gemmfill<<<GEMM_GRID + FILL_GRID, T>>>(x, W1, ei, w);
    k_layer1<<<(N_NODES * 32 + T - 1) / T, T>>>(b1, W2);
    k_layer2<<<(N_NODES * 32 + T - 1) / T, T>>>(b2, out);
}

// round 8
// speedup vs baseline: 1.0690x; 1.0355x over previous
#include <cuda_runtime.h>
#include <cuda_bf16.h>

// 2-layer GCN via CSC build + gather aggregation.
// edge_index arrives as int32 (JAX x64 disabled).
// Ranks assigned by the counting atomic -> fill needs NO atomics.
// h is pre-scaled by dinv[row]; s is pre-scaled by dinv -> edge coef = raw w[e].
// k_init -> k_edge_count -> k_scan -> k_gemmfill -> k_layer1 -> k_layer2

#define N_NODES 100000
#define N_EDGES 1600000
#define C 64
#define SCAN_B 256
#define NB ((N_NODES + SCAN_B - 1) / SCAN_B)   // 391
#define W_SCALE 67108864.0f                    // 2^26 fixed-point for w
#define W_MASK  ((1ULL << 40) - 1ULL)
#define GB 64
#define GEMM_GRID ((N_NODES + GB - 1) / GB)    // 1563
#define FILL_GRID ((N_EDGES / 2 + 255) / 256)  // 3125

__device__ unsigned long long g_pack[N_NODES];   // {cnt:24 | sum_w fixed:40}
__device__ float g_dinv[N_NODES];
__device__ int   g_off[N_NODES + 1];
__device__ unsigned long long g_scanstate[NB];   // {flag:2 | value:32}
__device__ __align__(16) unsigned g_rank[N_EDGES];
__device__ __align__(16) uint2 g_edge[N_EDGES];           // {src, w bits}
__device__ __align__(16) float g_h[(size_t)N_NODES * C];  // h' = (x@W1)*dinv[row]
__device__ float g_s[N_NODES];                            // s' = s*dinv

__global__ void k_init() {
    int i = blockIdx.x * blockDim.x + threadIdx.x;
    if (i < N_NODES) g_pack[i] = 0ULL;
    if (i < NB) g_scanstate[i] = 0ULL;
}

// one packed u64 atomic per edge; prev count == rank within destination bucket
__global__ void k_edge_count(const int* __restrict__ ei,
                             const float* __restrict__ w) {
    int t = blockIdx.x * blockDim.x + threadIdx.x;
    if (t * 2 >= N_EDGES) return;
    int2   cc = *reinterpret_cast<const int2*>(ei + N_EDGES + t * 2);
    float2 ww = *reinterpret_cast<const float2*>(w + t * 2);
    unsigned long long p0 = (1ULL << 40) + (unsigned long long)(ww.x * W_SCALE);
    unsigned long long p1 = (1ULL << 40) + (unsigned long long)(ww.y * W_SCALE);
    unsigned long long prev0 = atomicAdd(&g_pack[cc.x], p0);
    unsigned long long prev1 = atomicAdd(&g_pack[cc.y], p1);
    uint2 rk = make_uint2((unsigned)(prev0 >> 40), (unsigned)(prev1 >> 40));
    *reinterpret_cast<uint2*>(g_rank + t * 2) = rk;
}

// fused: dinv + exclusive scan of counts (decoupled lookback)
__global__ void k_scan() {
    int t = threadIdx.x;
    int b = blockIdx.x;
    int i = b * SCAN_B + t;
    int lane = t & 31, wid = t >> 5;

    int cnt = 0;
    if (i < N_NODES) {
        unsigned long long p = g_pack[i];
        cnt = (int)(p >> 40);
        float deg = 1.0f + (float)(p & W_MASK) * (1.0f / W_SCALE);
        g_dinv[i] = rsqrtf(deg);
    }

    int v = cnt;
#pragma unroll
    for (int o = 1; o < 32; o <<= 1) {
        int y = __shfl_up_sync(0xffffffffu, v, o);
        if (lane >= o) v += y;
    }
    __shared__ int wsum[8];
    if (lane == 31) wsum[wid] = v;
    __syncthreads();
    if (wid == 0) {
        int x = (lane < 8) ? wsum[lane] : 0;
#pragma unroll
        for (int o = 1; o < 8; o <<= 1) {
            int y = __shfl_up_sync(0xffffffffu, x, o);
            if (lane >= o) x += y;
        }
        if (lane < 8) wsum[lane] = x;
    }
    __syncthreads();
    int incl = v + ((wid > 0) ? wsum[wid - 1] : 0);
    int blocktotal = wsum[7];

    __shared__ int sh_prefix;
    if (t == 0) {
        if (b == 0) {
            sh_prefix = 0;
            atomicExch(&g_scanstate[0], (2ULL << 62) | (unsigned)blocktotal);
        } else {
            atomicExch(&g_scanstate[b], (1ULL << 62) | (unsigned)blocktotal);
            int ex = 0;
            int j = b - 1;
            for (;;) {
                unsigned long long s;
                do { s = atomicAdd(&g_scanstate[j], 0ULL); } while ((s >> 62) == 0ULL);
                ex += (int)(s & 0xffffffffULL);
                if ((s >> 62) == 2ULL) break;
                j--;
            }
            sh_prefix = ex;
            atomicExch(&g_scanstate[b], (2ULL << 62) | (unsigned)(ex + blocktotal));
        }
    }
    __syncthreads();

    if (i < N_NODES) g_off[i] = sh_prefix + incl - cnt;   // exclusive
    if (i == 0) g_off[N_NODES] = N_EDGES;
}

// grid-split kernel: blocks [0, GEMM_GRID) compute h' = (x@W1)*dinv,
// blocks [GEMM_GRID, ...) fill the CSC edge array (no atomics).
__global__ void k_gemmfill(const float* __restrict__ x,
                           const float* __restrict__ W1,
                           const int* __restrict__ ei,
                           const float* __restrict__ w) {
    __shared__ float xs[GB][72];
    __shared__ float Ws[64][64];
    int t = threadIdx.x;

    if (blockIdx.x >= GEMM_GRID) {
        int t2 = (blockIdx.x - GEMM_GRID) * 256 + t;
        if (t2 * 2 >= N_EDGES) return;
        int2   rr = *reinterpret_cast<const int2*>(ei + t2 * 2);
        int2   cc = *reinterpret_cast<const int2*>(ei + N_EDGES + t2 * 2);
        float2 ww = *reinterpret_cast<const float2*>(w + t2 * 2);
        uint2  rk = *reinterpret_cast<const uint2*>(g_rank + t2 * 2);
        int p0 = g_off[cc.x] + (int)rk.x;
        int p1 = g_off[cc.y] + (int)rk.y;
        g_edge[p0] = make_uint2((unsigned)rr.x, __float_as_uint(ww.x));
        g_edge[p1] = make_uint2((unsigned)rr.y, __float_as_uint(ww.y));
        return;
    }

    int nb = blockIdx.x * GB;
#pragma unroll
    for (int i = 0; i < 16; i++)
        ((float*)Ws)[t + i * 256] = W1[t + i * 256];
    {
        int nd = t >> 2;
        int q  = (t & 3) * 16;
        int node = nb + nd;
        if (node < N_NODES) {
            const float* xp = x + (size_t)node * 64 + q;
            float4 v0 = *(const float4*)(xp);
            float4 v1 = *(const float4*)(xp + 4);
            float4 v2 = *(const float4*)(xp + 8);
            float4 v3 = *(const float4*)(xp + 12);
            *(float4*)&xs[nd][q]      = v0;
            *(float4*)&xs[nd][q + 4]  = v1;
            *(float4*)&xs[nd][q + 8]  = v2;
            *(float4*)&xs[nd][q + 12] = v3;
        }
    }
    __syncthreads();

    int ch4 = (t & 15) * 4;
    int nd0 = (t >> 4) * 4;

    float acc[4][4];
#pragma unroll
    for (int i = 0; i < 4; i++)
#pragma unroll
        for (int j = 0; j < 4; j++) acc[i][j] = 0.0f;

#pragma unroll 4
    for (int k = 0; k < 64; k++) {
        float4 wv = *(const float4*)&Ws[k][ch4];
        float x0 = xs[nd0 + 0][k];
        float x1 = xs[nd0 + 1][k];
        float x2 = xs[nd0 + 2][k];
        float x3 = xs[nd0 + 3][k];
        acc[0][0] = fmaf(x0, wv.x, acc[0][0]); acc[0][1] = fmaf(x0, wv.y, acc[0][1]);
        acc[0][2] = fmaf(x0, wv.z, acc[0][2]); acc[0][3] = fmaf(x0, wv.w, acc[0][3]);
        acc[1][0] = fmaf(x1, wv.x, acc[1][0]); acc[1][1] = fmaf(x1, wv.y, acc[1][1]);
        acc[1][2] = fmaf(x1, wv.z, acc[1][2]); acc[1][3] = fmaf(x1, wv.w, acc[1][3]);
        acc[2][0] = fmaf(x2, wv.x, acc[2][0]); acc[2][1] = fmaf(x2, wv.y, acc[2][1]);
        acc[2][2] = fmaf(x2, wv.z, acc[2][2]); acc[2][3] = fmaf(x2, wv.w, acc[2][3]);
        acc[3][0] = fmaf(x3, wv.x, acc[3][0]); acc[3][1] = fmaf(x3, wv.y, acc[3][1]);
        acc[3][2] = fmaf(x3, wv.z, acc[3][2]); acc[3][3] = fmaf(x3, wv.w, acc[3][3]);
    }

#pragma unroll
    for (int i = 0; i < 4; i++) {
        int node = nb + nd0 + i;
        if (node < N_NODES) {
            float di = g_dinv[node];
            float4 o = make_float4(acc[i][0] * di, acc[i][1] * di,
                                   acc[i][2] * di, acc[i][3] * di);
            *(float4*)(g_h + (size_t)node * 64 + ch4) = o;
        }
    }
}

// fused layer1 aggregate + relu + layer2 projection. one warp per node.
// half-warp scheme: lanes 0-15 / 16-31 each own one edge per step; each
// lane loads float4 (half-warp covers the full 256B row, coalesced).
__global__ void k_layer1(const float* __restrict__ b1,
                         const float* __restrict__ W2) {
    int n = (blockIdx.x * blockDim.x + threadIdx.x) >> 5;
    int lane = threadIdx.x & 31;
    if (n >= N_NODES) return;
    int half = lane >> 4;       // 0 or 1
    int sub  = lane & 15;       // float4 slot within row

    int idx = g_off[n];
    int end = g_off[n + 1];
    const float4* __restrict__ hp4 = reinterpret_cast<const float4*>(g_h);

    float4 acc = make_float4(0.f, 0.f, 0.f, 0.f);
    for (; idx + 8 <= end; idx += 8) {
        uint2 e0 = g_edge[idx + half + 0];
        uint2 e1 = g_edge[idx + half + 2];
        uint2 e2 = g_edge[idx + half + 4];
        uint2 e3 = g_edge[idx + half + 6];
        float4 h0 = hp4[e0.x * 16u + sub];
        float4 h1 = hp4[e1.x * 16u + sub];
        float4 h2 = hp4[e2.x * 16u + sub];
        float4 h3 = hp4[e3.x * 16u + sub];
        float c0 = __uint_as_float(e0.y), c1 = __uint_as_float(e1.y);
        float c2 = __uint_as_float(e2.y), c3 = __uint_as_float(e3.y);
        acc.x = fmaf(c0, h0.x, acc.x); acc.y = fmaf(c0, h0.y, acc.y);
        acc.z = fmaf(c0, h0.z, acc.z); acc.w = fmaf(c0, h0.w, acc.w);
        acc.x = fmaf(c1, h1.x, acc.x); acc.y = fmaf(c1, h1.y, acc.y);
        acc.z = fmaf(c1, h1.z, acc.z); acc.w = fmaf(c1, h1.w, acc.w);
        acc.x = fmaf(c2, h2.x, acc.x); acc.y = fmaf(c2, h2.y, acc.y);
        acc.z = fmaf(c2, h2.z, acc.z); acc.w = fmaf(c2, h2.w, acc.w);
        acc.x = fmaf(c3, h3.x, acc.x); acc.y = fmaf(c3, h3.y, acc.y);
        acc.z = fmaf(c3, h3.z, acc.z); acc.w = fmaf(c3, h3.w, acc.w);
    }
    for (; idx < end; idx += 2) {
        int my = idx + half;
        if (my < end) {
            uint2 e = g_edge[my];
            float4 hv = hp4[e.x * 16u + sub];
            float cf = __uint_as_float(e.y);
            acc.x = fmaf(cf, hv.x, acc.x); acc.y = fmaf(cf, hv.y, acc.y);
            acc.z = fmaf(cf, hv.z, acc.z); acc.w = fmaf(cf, hv.w, acc.w);
        }
    }

    // combine the two half-warps (lanes i and i+16 hold the same channels)
    acc.x += __shfl_xor_sync(0xffffffffu, acc.x, 16);
    acc.y += __shfl_xor_sync(0xffffffffu, acc.y, 16);
    acc.z += __shfl_xor_sync(0xffffffffu, acc.z, 16);
    acc.w += __shfl_xor_sync(0xffffffffu, acc.w, 16);

    float din = g_dinv[n];
    float4 hn = hp4[(unsigned)n * 16u + sub];
    float4 bb = reinterpret_cast<const float4*>(b1)[sub];
    float4 w2 = reinterpret_cast<const float4*>(W2)[sub];
    float v0 = fmaxf(fmaf(acc.x + hn.x, din, bb.x), 0.0f);
    float v1 = fmaxf(fmaf(acc.y + hn.y, din, bb.y), 0.0f);
    float v2 = fmaxf(fmaf(acc.z + hn.z, din, bb.z), 0.0f);
    float v3 = fmaxf(fmaf(acc.w + hn.w, din, bb.w), 0.0f);
    float s = v0 * w2.x + v1 * w2.y + v2 * w2.z + v3 * w2.w;
#pragma unroll
    for (int off = 8; off > 0; off >>= 1)
        s += __shfl_xor_sync(0xffffffffu, s, off);
    if (lane == 0) g_s[n] = s * din;   // store s' = s*dinv
}

// layer2 gather: half-warp (16 lanes) per node; s is pre-scaled.
__global__ void k_layer2(const float* __restrict__ b2,
                         float* __restrict__ out) {
    int n = (blockIdx.x * blockDim.x + threadIdx.x) >> 4;
    int sub = threadIdx.x & 15;
    if (n >= N_NODES) return;

    int begin = g_off[n];
    int end   = g_off[n + 1];

    float acc = 0.0f;
    for (int idx = begin + sub; idx < end; idx += 16) {
        uint2 em = g_edge[idx];
        acc = fmaf(__uint_as_float(em.y), g_s[em.x], acc);
    }
#pragma unroll
    for (int off = 8; off > 0; off >>= 1)
        acc += __shfl_xor_sync(0xffffffffu, acc, off);

    if (sub == 0) {
        float din = g_dinv[n];
        out[n] = fmaf(acc + g_s[n], din, b2[0]);
    }
}

extern "C" void kernel_launch(void* const* d_in, const int* in_sizes, int n_in,
                              void* d_out, int out_size) {
    const float* x  = (const float*)d_in[0];
    const int*   ei = (const int*)d_in[1];
    const float* w  = (const float*)d_in[2];
    const float* W1 = (const float*)d_in[3];
    const float* b1 = (const float*)d_in[4];
    const float* W2 = (const float*)d_in[5];
    const float* b2 = (const float*)d_in[6];
    float* out = (float*)d_out;

    const int T = 256;
    k_init<<<NB, T>>>();
    k_edge_count<<<(N_EDGES / 2 + T - 1) / T, T>>>(ei, w);
    k_scan<<<NB, SCAN_B>>>();
    k_gemmfill<<<GEMM_GRID + FILL_GRID, T>>>(x, W1, ei, w);
    k_layer1<<<(N_NODES * 32 + T - 1) / T, T>>>(b1, W2);
    k_layer2<<<(N_NODES * 16 + T - 1) / T, T>>>(b2, out);
}

// round 10
// speedup vs baseline: 1.1054x; 1.0341x over previous
#include <cuda_runtime.h>
#include <cuda_fp16.h>

// 2-layer GCN via CSC build + gather aggregation.
// edge_index arrives as int32 (JAX x64 disabled).
// h' = (x@W1)*dinv stored as FP16 (one 128B cacheline per node row);
// fp32 accumulation everywhere. s' = s*dinv stored fp32.
// k_init -> k_edge_count -> k_scan -> k_gemmfill -> k_layer1 -> k_layer2

#define N_NODES 100000
#define N_EDGES 1600000
#define C 64
#define SCAN_B 256
#define NB ((N_NODES + SCAN_B - 1) / SCAN_B)   // 391
#define W_SCALE 67108864.0f                    // 2^26 fixed-point for w
#define W_MASK  ((1ULL << 40) - 1ULL)
#define GB 64
#define GEMM_GRID ((N_NODES + GB - 1) / GB)    // 1563
#define FILL_GRID ((N_EDGES / 2 + 255) / 256)  // 3125

__device__ unsigned long long g_pack[N_NODES];   // {cnt:24 | sum_w fixed:40}
__device__ float g_dinv[N_NODES];
__device__ int   g_off[N_NODES + 1];
__device__ unsigned long long g_scanstate[NB];   // {flag:2 | value:32}
__device__ __align__(16) unsigned g_rank[N_EDGES];
__device__ __align__(16) uint2 g_edge[N_EDGES];            // {src, w bits}
__device__ __align__(16) __half g_hh[(size_t)N_NODES * C]; // h' fp16, 128B/row
__device__ float g_s[N_NODES];                             // s' = s*dinv

__device__ __forceinline__ unsigned h2_bits(__half2 v) {
    return *reinterpret_cast<unsigned*>(&v);
}

__global__ void k_init() {
    int i = blockIdx.x * blockDim.x + threadIdx.x;
    if (i < N_NODES) g_pack[i] = 0ULL;
    if (i < NB) g_scanstate[i] = 0ULL;
}

// one packed u64 atomic per edge; prev count == rank within destination bucket
__global__ void k_edge_count(const int* __restrict__ ei,
                             const float* __restrict__ w) {
    int t = blockIdx.x * blockDim.x + threadIdx.x;
    if (t * 2 >= N_EDGES) return;
    int2   cc = *reinterpret_cast<const int2*>(ei + N_EDGES + t * 2);
    float2 ww = *reinterpret_cast<const float2*>(w + t * 2);
    unsigned long long p0 = (1ULL << 40) + (unsigned long long)(ww.x * W_SCALE);
    unsigned long long p1 = (1ULL << 40) + (unsigned long long)(ww.y * W_SCALE);
    unsigned long long prev0 = atomicAdd(&g_pack[cc.x], p0);
    unsigned long long prev1 = atomicAdd(&g_pack[cc.y], p1);
    uint2 rk = make_uint2((unsigned)(prev0 >> 40), (unsigned)(prev1 >> 40));
    *reinterpret_cast<uint2*>(g_rank + t * 2) = rk;
}

// fused: dinv + exclusive scan of counts (decoupled lookback)
__global__ void k_scan() {
    int t = threadIdx.x;
    int b = blockIdx.x;
    int i = b * SCAN_B + t;
    int lane = t & 31, wid = t >> 5;

    int cnt = 0;
    if (i < N_NODES) {
        unsigned long long p = g_pack[i];
        cnt = (int)(p >> 40);
        float deg = 1.0f + (float)(p & W_MASK) * (1.0f / W_SCALE);
        g_dinv[i] = rsqrtf(deg);
    }

    int v = cnt;
#pragma unroll
    for (int o = 1; o < 32; o <<= 1) {
        int y = __shfl_up_sync(0xffffffffu, v, o);
        if (lane >= o) v += y;
    }
    __shared__ int wsum[8];
    if (lane == 31) wsum[wid] = v;
    __syncthreads();
    if (wid == 0) {
        int x = (lane < 8) ? wsum[lane] : 0;
#pragma unroll
        for (int o = 1; o < 8; o <<= 1) {
            int y = __shfl_up_sync(0xffffffffu, x, o);
            if (lane >= o) x += y;
        }
        if (lane < 8) wsum[lane] = x;
    }
    __syncthreads();
    int incl = v + ((wid > 0) ? wsum[wid - 1] : 0);
    int blocktotal = wsum[7];

    __shared__ int sh_prefix;
    if (t == 0) {
        if (b == 0) {
            sh_prefix = 0;
            atomicExch(&g_scanstate[0], (2ULL << 62) | (unsigned)blocktotal);
        } else {
            atomicExch(&g_scanstate[b], (1ULL << 62) | (unsigned)blocktotal);
            int ex = 0;
            int j = b - 1;
            for (;;) {
                unsigned long long s;
                do { s = atomicAdd(&g_scanstate[j], 0ULL); } while ((s >> 62) == 0ULL);
                ex += (int)(s & 0xffffffffULL);
                if ((s >> 62) == 2ULL) break;
                j--;
            }
            sh_prefix = ex;
            atomicExch(&g_scanstate[b], (2ULL << 62) | (unsigned)(ex + blocktotal));
        }
    }
    __syncthreads();

    if (i < N_NODES) g_off[i] = sh_prefix + incl - cnt;   // exclusive
    if (i == 0) g_off[N_NODES] = N_EDGES;
}

// grid-split kernel: blocks [0, GEMM_GRID) compute h' = (x@W1)*dinv -> fp16,
// blocks [GEMM_GRID, ...) fill the CSC edge array (no atomics).
__global__ void k_gemmfill(const float* __restrict__ x,
                           const float* __restrict__ W1,
                           const int* __restrict__ ei,
                           const float* __restrict__ w) {
    __shared__ float xs[GB][72];
    __shared__ float Ws[64][64];
    int t = threadIdx.x;

    if (blockIdx.x >= GEMM_GRID) {
        int t2 = (blockIdx.x - GEMM_GRID) * 256 + t;
        if (t2 * 2 >= N_EDGES) return;
        int2   rr = *reinterpret_cast<const int2*>(ei + t2 * 2);
        int2   cc = *reinterpret_cast<const int2*>(ei + N_EDGES + t2 * 2);
        float2 ww = *reinterpret_cast<const float2*>(w + t2 * 2);
        uint2  rk = *reinterpret_cast<const uint2*>(g_rank + t2 * 2);
        int p0 = g_off[cc.x] + (int)rk.x;
        int p1 = g_off[cc.y] + (int)rk.y;
        g_edge[p0] = make_uint2((unsigned)rr.x, __float_as_uint(ww.x));
        g_edge[p1] = make_uint2((unsigned)rr.y, __float_as_uint(ww.y));
        return;
    }

    int nb = blockIdx.x * GB;
#pragma unroll
    for (int i = 0; i < 16; i++)
        ((float*)Ws)[t + i * 256] = W1[t + i * 256];
    {
        int nd = t >> 2;
        int q  = (t & 3) * 16;
        int node = nb + nd;
        if (node < N_NODES) {
            const float* xp = x + (size_t)node * 64 + q;
            float4 v0 = *(const float4*)(xp);
            float4 v1 = *(const float4*)(xp + 4);
            float4 v2 = *(const float4*)(xp + 8);
            float4 v3 = *(const float4*)(xp + 12);
            *(float4*)&xs[nd][q]      = v0;
            *(float4*)&xs[nd][q + 4]  = v1;
            *(float4*)&xs[nd][q + 8]  = v2;
            *(float4*)&xs[nd][q + 12] = v3;
        }
    }
    __syncthreads();

    int ch4 = (t & 15) * 4;
    int nd0 = (t >> 4) * 4;

    float acc[4][4];
#pragma unroll
    for (int i = 0; i < 4; i++)
#pragma unroll
        for (int j = 0; j < 4; j++) acc[i][j] = 0.0f;

#pragma unroll 4
    for (int k = 0; k < 64; k++) {
        float4 wv = *(const float4*)&Ws[k][ch4];
        float x0 = xs[nd0 + 0][k];
        float x1 = xs[nd0 + 1][k];
        float x2 = xs[nd0 + 2][k];
        float x3 = xs[nd0 + 3][k];
        acc[0][0] = fmaf(x0, wv.x, acc[0][0]); acc[0][1] = fmaf(x0, wv.y, acc[0][1]);
        acc[0][2] = fmaf(x0, wv.z, acc[0][2]); acc[0][3] = fmaf(x0, wv.w, acc[0][3]);
        acc[1][0] = fmaf(x1, wv.x, acc[1][0]); acc[1][1] = fmaf(x1, wv.y, acc[1][1]);
        acc[1][2] = fmaf(x1, wv.z, acc[1][2]); acc[1][3] = fmaf(x1, wv.w, acc[1][3]);
        acc[2][0] = fmaf(x2, wv.x, acc[2][0]); acc[2][1] = fmaf(x2, wv.y, acc[2][1]);
        acc[2][2] = fmaf(x2, wv.z, acc[2][2]); acc[2][3] = fmaf(x2, wv.w, acc[2][3]);
        acc[3][0] = fmaf(x3, wv.x, acc[3][0]); acc[3][1] = fmaf(x3, wv.y, acc[3][1]);
        acc[3][2] = fmaf(x3, wv.z, acc[3][2]); acc[3][3] = fmaf(x3, wv.w, acc[3][3]);
    }

#pragma unroll
    for (int i = 0; i < 4; i++) {
        int node = nb + nd0 + i;
        if (node < N_NODES) {
            float di = g_dinv[node];
            __half2 p0 = __floats2half2_rn(acc[i][0] * di, acc[i][1] * di);
            __half2 p1 = __floats2half2_rn(acc[i][2] * di, acc[i][3] * di);
            uint2 st = make_uint2(h2_bits(p0), h2_bits(p1));
            *reinterpret_cast<uint2*>(g_hh + (size_t)node * 64 + ch4) = st;
        }
    }
}

// fused layer1 aggregate + relu + layer2 projection. one warp per node.
// quarter-warp per edge: 8 lanes x uint4 (8 fp16) = full 128B row (1 line).
// 4 edges in flight per warp step; fp32 accumulation.
__global__ void k_layer1(const float* __restrict__ b1,
                         const float* __restrict__ W2) {
    int n = (blockIdx.x * blockDim.x + threadIdx.x) >> 5;
    int lane = threadIdx.x & 31;
    if (n >= N_NODES) return;
    int quarter = lane >> 3;    // 0..3: which edge in the 4-group
    int sub     = lane & 7;     // uint4 slot within row (8 halves each)

    int idx = g_off[n];
    int end = g_off[n + 1];
    const uint4* __restrict__ hp = reinterpret_cast<const uint4*>(g_hh);

    float a[8];
#pragma unroll
    for (int j = 0; j < 8; j++) a[j] = 0.0f;

    for (; idx + 4 <= end; idx += 4) {
        uint2 e = g_edge[idx + quarter];
        uint4 hv = hp[e.x * 8u + sub];
        float cf = __uint_as_float(e.y);
        float2 f0 = __half22float2(*reinterpret_cast<__half2*>(&hv.x));
        float2 f1 = __half22float2(*reinterpret_cast<__half2*>(&hv.y));
        float2 f2 = __half22float2(*reinterpret_cast<__half2*>(&hv.z));
        float2 f3 = __half22float2(*reinterpret_cast<__half2*>(&hv.w));
        a[0] = fmaf(cf, f0.x, a[0]); a[1] = fmaf(cf, f0.y, a[1]);
        a[2] = fmaf(cf, f1.x, a[2]); a[3] = fmaf(cf, f1.y, a[3]);
        a[4] = fmaf(cf, f2.x, a[4]); a[5] = fmaf(cf, f2.y, a[5]);
        a[6] = fmaf(cf, f3.x, a[6]); a[7] = fmaf(cf, f3.y, a[7]);
    }
    if (idx < end) {
        int my = idx + quarter;
        if (my < end) {
            uint2 e = g_edge[my];
            uint4 hv = hp[e.x * 8u + sub];
            float cf = __uint_as_float(e.y);
            float2 f0 = __half22float2(*reinterpret_cast<__half2*>(&hv.x));
            float2 f1 = __half22float2(*reinterpret_cast<__half2*>(&hv.y));
            float2 f2 = __half22float2(*reinterpret_cast<__half2*>(&hv.z));
            float2 f3 = __half22float2(*reinterpret_cast<__half2*>(&hv.w));
            a[0] = fmaf(cf, f0.x, a[0]); a[1] = fmaf(cf, f0.y, a[1]);
            a[2] = fmaf(cf, f1.x, a[2]); a[3] = fmaf(cf, f1.y, a[3]);
            a[4] = fmaf(cf, f2.x, a[4]); a[5] = fmaf(cf, f2.y, a[5]);
            a[6] = fmaf(cf, f3.x, a[6]); a[7] = fmaf(cf, f3.y, a[7]);
        }
    }

    // combine the 4 quarter-warps (lanes sub, sub+8, sub+16, sub+24 same channels)
#pragma unroll
    for (int j = 0; j < 8; j++) {
        a[j] += __shfl_xor_sync(0xffffffffu, a[j], 8);
        a[j] += __shfl_xor_sync(0xffffffffu, a[j], 16);
    }

    float din = g_dinv[n];
    uint4 hnv = hp[(unsigned)n * 8u + sub];
    float2 hn0 = __half22float2(*reinterpret_cast<__half2*>(&hnv.x));
    float2 hn1 = __half22float2(*reinterpret_cast<__half2*>(&hnv.y));
    float2 hn2 = __half22float2(*reinterpret_cast<__half2*>(&hnv.z));
    float2 hn3 = __half22float2(*reinterpret_cast<__half2*>(&hnv.w));
    float hn[8] = {hn0.x, hn0.y, hn1.x, hn1.y, hn2.x, hn2.y, hn3.x, hn3.y};

    float4 bA = reinterpret_cast<const float4*>(b1)[sub * 2];
    float4 bB = reinterpret_cast<const float4*>(b1)[sub * 2 + 1];
    float4 wA = reinterpret_cast<const float4*>(W2)[sub * 2];
    float4 wB = reinterpret_cast<const float4*>(W2)[sub * 2 + 1];
    float bb[8] = {bA.x, bA.y, bA.z, bA.w, bB.x, bB.y, bB.z, bB.w};
    float w2[8] = {wA.x, wA.y, wA.z, wA.w, wB.x, wB.y, wB.z, wB.w};

    float s = 0.0f;
#pragma unroll
    for (int j = 0; j < 8; j++) {
        float v = fmaxf(fmaf(a[j] + hn[j], din, bb[j]), 0.0f);
        s = fmaf(v, w2[j], s);
    }
#pragma unroll
    for (int off = 4; off > 0; off >>= 1)
        s += __shfl_xor_sync(0xffffffffu, s, off);
    if (lane == 0) g_s[n] = s * din;   // store s' = s*dinv
}

// layer2 gather: half-warp (16 lanes) per node; s is pre-scaled.
__global__ void k_layer2(const float* __restrict__ b2,
                         float* __restrict__ out) {
    int n = (blockIdx.x * blockDim.x + threadIdx.x) >> 4;
    int sub = threadIdx.x & 15;
    if (n >= N_NODES) return;

    int begin = g_off[n];
    int end   = g_off[n + 1];

    float acc = 0.0f;
    for (int idx = begin + sub; idx < end; idx += 16) {
        uint2 em = g_edge[idx];
        acc = fmaf(__uint_as_float(em.y), g_s[em.x], acc);
    }
#pragma unroll
    for (int off = 8; off > 0; off >>= 1)
        acc += __shfl_xor_sync(0xffffffffu, acc, off);

    if (sub == 0) {
        float din = g_dinv[n];
        out[n] = fmaf(acc + g_s[n], din, b2[0]);
    }
}

extern "C" void kernel_launch(void* const* d_in, const int* in_sizes, int n_in,
                              void* d_out, int out_size) {
    const float* x  = (const float*)d_in[0];
    const int*   ei = (const int*)d_in[1];
    const float* w  = (const float*)d_in[2];
    const float* W1 = (const float*)d_in[3];
    const float* b1 = (const float*)d_in[4];
    const float* W2 = (const float*)d_in[5];
    const float* b2 = (const float*)d_in[6];
    float* out = (float*)d_out;

    const int T = 256;
    k_init<<<NB, T>>>();
    k_edge_count<<<(N_EDGES / 2 + T - 1) / T, T>>>(ei, w);
    k_scan<<<NB, SCAN_B>>>();
    k_gemmfill<<<GEMM_GRID + FILL_GRID, T>>>(x, W1, ei, w);
    k_layer1<<<(N_NODES * 32 + T - 1) / T, T>>>(b1, W2);
    k_layer2<<<(N_NODES * 16 + T - 1) / T, T>>>(b2, out);
}